// round 1
// baseline (speedup 1.0000x reference)
#include <cuda_runtime.h>

// Problem shape (fixed for this dataset entry)
#define BB 8
#define CC 81
#define HH 96
#define WW 320
#define NN 16

#define ALPHA_F   0.25f
#define FG_W_F    13.0f
#define BG_W_F    1.0f
#define DEPTH_MIN_F 0.001f
#define DEPTH_MAX_F 60.0f
#define NUM_BINS_I  80

__global__ __launch_bounds__(256, 4) void ddn_loss_kernel(
    const float* __restrict__ logits,   // (B,C,H,W)
    const float* __restrict__ boxes,    // (B*N,4) u1,v1,u2,v2
    const float* __restrict__ depths,   // (B*N,)
    float* __restrict__ out)            // scalar
{
    __shared__ int   sbu1[NN], sbv1[NN], sbu2[NN], sbv2[NN];
    __shared__ float sdep[NN];
    __shared__ float sred[8];

    const int HW4 = (HH * WW) / 4;           // 7680 (multiple of 256 -> block stays in one batch)
    const int g   = blockIdx.x * 256 + threadIdx.x;   // 0..61439
    const int b   = g / HW4;
    const int rem = g - b * HW4;
    const int h   = rem / (WW / 4);
    const int w0  = (rem - h * (WW / 4)) * 4;

    if (threadIdx.x < NN) {
        const int i = b * NN + threadIdx.x;
        const float u1 = boxes[4 * i + 0];
        const float v1 = boxes[4 * i + 1];
        const float u2 = boxes[4 * i + 2];
        const float v2 = boxes[4 * i + 3];
        sbu1[threadIdx.x] = (int)floorf(u1);
        sbv1[threadIdx.x] = (int)floorf(v1);
        sbu2[threadIdx.x] = (int)ceilf(u2);
        sbv2[threadIdx.x] = (int)ceilf(v2);
        sdep[threadIdx.x] = depths[i];
    }
    __syncthreads();

    // ---- Rasterize + LID binning for this thread's 4 pixels ----
    int   tgt[4];
    float wgt[4];
#pragma unroll
    for (int j = 0; j < 4; j++) {
        const int w = w0 + j;
        float dmin = 1e10f;
        bool  fg   = false;
#pragma unroll
        for (int i = 0; i < NN; i++) {
            const bool cov = (h >= sbv1[i]) & (h < sbv2[i]) &
                             (w >= sbu1[i]) & (w < sbu2[i]);
            if (cov) { fg = true; dmin = fminf(dmin, sdep[i]); }
        }
        const float d = fg ? dmin : 0.0f;
        const float bin_size = 2.0f * (DEPTH_MAX_F - DEPTH_MIN_F)
                               / ((float)NUM_BINS_I * (1.0f + (float)NUM_BINS_I));
        float idx = -0.5f + 0.5f * sqrtf(1.0f + 8.0f * (d - DEPTH_MIN_F) / bin_size);
        if (!(idx >= 0.0f) || idx > (float)NUM_BINS_I) idx = (float)NUM_BINS_I;
        tgt[j] = (int)idx;                 // truncation toward zero, matches reference
        wgt[j] = fg ? FG_W_F : BG_W_F;
    }

    // ---- Stream the 81 channels once: sum-exp + grab target logit ----
    float s0 = 0.f, s1 = 0.f, s2 = 0.f, s3 = 0.f;
    float xt0 = 0.f, xt1 = 0.f, xt2 = 0.f, xt3 = 0.f;

    const float4* __restrict__ p =
        (const float4*)(logits + (long)b * CC * HH * WW + (long)h * WW + w0);
    const long stride4 = (HH * WW) / 4;    // float4 units between channel planes

#pragma unroll 9
    for (int c = 0; c < CC; c++) {
        const float4 x = p[(long)c * stride4];
        s0 += __expf(x.x); if (c == tgt[0]) xt0 = x.x;
        s1 += __expf(x.y); if (c == tgt[1]) xt1 = x.y;
        s2 += __expf(x.z); if (c == tgt[2]) xt2 = x.z;
        s3 += __expf(x.w); if (c == tgt[3]) xt3 = x.w;
    }

    // ---- Focal loss per pixel, weighted ----
    float local = 0.f;
    {
        float lp, pt;
        lp = xt0 - __logf(s0); pt = __expf(lp);
        local += wgt[0] * (-ALPHA_F * (1.f - pt) * (1.f - pt) * lp);
        lp = xt1 - __logf(s1); pt = __expf(lp);
        local += wgt[1] * (-ALPHA_F * (1.f - pt) * (1.f - pt) * lp);
        lp = xt2 - __logf(s2); pt = __expf(lp);
        local += wgt[2] * (-ALPHA_F * (1.f - pt) * (1.f - pt) * lp);
        lp = xt3 - __logf(s3); pt = __expf(lp);
        local += wgt[3] * (-ALPHA_F * (1.f - pt) * (1.f - pt) * lp);
    }

    // ---- Block reduction -> one atomic per block ----
#pragma unroll
    for (int o = 16; o > 0; o >>= 1)
        local += __shfl_xor_sync(0xffffffffu, local, o);
    if ((threadIdx.x & 31) == 0) sred[threadIdx.x >> 5] = local;
    __syncthreads();
    if (threadIdx.x < 8) {
        float v = sred[threadIdx.x];
#pragma unroll
        for (int o = 4; o > 0; o >>= 1)
            v += __shfl_xor_sync(0x000000ffu, v, o);
        if (threadIdx.x == 0) {
            const float inv_np = 1.0f / (float)(BB * HH * WW);
            atomicAdd(out, v * inv_np);
        }
    }
}

extern "C" void kernel_launch(void* const* d_in, const int* in_sizes, int n_in,
                              void* d_out, int out_size) {
    const float* logits = (const float*)d_in[0];   // depth_logits (B,C,H,W) f32
    const float* boxes  = (const float*)d_in[1];   // gt_boxes2d (B*N,4) f32
    // d_in[2] = num_gt_per_img (scalar int, constant 16 for this shape)
    const float* depths = (const float*)d_in[3];   // gt_center_depth (B*N,) f32
    float* out = (float*)d_out;

    cudaMemsetAsync(out, 0, sizeof(float), 0);

    const int total_groups = BB * HH * WW / 4;     // 61440
    const int threads = 256;
    const int blocks  = total_groups / threads;    // 240
    ddn_loss_kernel<<<blocks, threads>>>(logits, boxes, depths, out);
}

// round 2
// speedup vs baseline: 1.0565x; 1.0565x over previous
#include <cuda_runtime.h>

// Problem shape (fixed for this dataset entry)
#define BB 8
#define CC 81
#define HH 96
#define WW 320
#define NN 16

#define ALPHA_F   0.25f
#define FG_W_F    13.0f
#define BG_W_F    1.0f
#define DEPTH_MIN_F 0.001f
#define DEPTH_MAX_F 60.0f
#define NUM_BINS_I  80

__global__ __launch_bounds__(256) void ddn_loss_kernel(
    const float* __restrict__ logits,   // (B,C,H,W)
    const float* __restrict__ boxes,    // (B*N,4) u1,v1,u2,v2
    const float* __restrict__ depths,   // (B*N,)
    float* __restrict__ out)            // scalar
{
    __shared__ int   sbu1[NN], sbv1[NN], sbu2[NN], sbv2[NN];
    __shared__ float sdep[NN];
    __shared__ float sred[8];

    const int HW  = HH * WW;                 // 30720
    const int HW2 = HW / 2;                  // 15360 (multiple of 256)
    const int g   = blockIdx.x * 256 + threadIdx.x;   // 0..122879
    const int b   = g / HW2;
    const int rem = g - b * HW2;
    const int h   = rem / (WW / 2);
    const int w0  = (rem - h * (WW / 2)) * 2;

    if (threadIdx.x < NN) {
        const int i = b * NN + threadIdx.x;
        sbu1[threadIdx.x] = (int)floorf(boxes[4 * i + 0]);
        sbv1[threadIdx.x] = (int)floorf(boxes[4 * i + 1]);
        sbu2[threadIdx.x] = (int)ceilf (boxes[4 * i + 2]);
        sbv2[threadIdx.x] = (int)ceilf (boxes[4 * i + 3]);
        sdep[threadIdx.x] = depths[i];
    }
    __syncthreads();

    // ---- Rasterize + LID binning for this thread's 2 pixels ----
    int   tgt[2];
    float wgt[2];
#pragma unroll
    for (int j = 0; j < 2; j++) {
        const int w = w0 + j;
        float dmin = 1e10f;
        bool  fg   = false;
#pragma unroll
        for (int i = 0; i < NN; i++) {
            const bool cov = (h >= sbv1[i]) & (h < sbv2[i]) &
                             (w >= sbu1[i]) & (w < sbu2[i]);
            if (cov) { fg = true; dmin = fminf(dmin, sdep[i]); }
        }
        const float d = fg ? dmin : 0.0f;
        const float bin_size = 2.0f * (DEPTH_MAX_F - DEPTH_MIN_F)
                               / ((float)NUM_BINS_I * (1.0f + (float)NUM_BINS_I));
        float idx = -0.5f + 0.5f * sqrtf(1.0f + 8.0f * (d - DEPTH_MIN_F) / bin_size);
        if (!(idx >= 0.0f) || idx > (float)NUM_BINS_I) idx = (float)NUM_BINS_I;
        tgt[j] = (int)idx;                 // truncation toward zero, matches reference
        wgt[j] = fg ? FG_W_F : BG_W_F;
    }

    // Base of this thread's pixel pair within batch b's plane stack
    const float* __restrict__ row = logits + (long)b * CC * HW + (long)h * WW + w0;

    // ---- Target logits fetched up front (same lines the stream will read) ----
    const float xt0 = row[(long)tgt[0] * HW];
    const float xt1 = row[(long)tgt[1] * HW + 1];

    // ---- Stream the 81 channels once: pure load + exp + add ----
    float s0 = 0.f, s1 = 0.f;
    const float2* __restrict__ p = (const float2*)row;
    const long stride2 = HW / 2;            // float2 units between channel planes

#pragma unroll 27
    for (int c = 0; c < CC; c++) {
        const float2 x = p[(long)c * stride2];
        s0 += __expf(x.x);
        s1 += __expf(x.y);
    }

    // ---- Focal loss per pixel, weighted ----
    float local = 0.f;
    {
        float lp, pt;
        lp = xt0 - __logf(s0); pt = __expf(lp);
        local += wgt[0] * (-ALPHA_F * (1.f - pt) * (1.f - pt) * lp);
        lp = xt1 - __logf(s1); pt = __expf(lp);
        local += wgt[1] * (-ALPHA_F * (1.f - pt) * (1.f - pt) * lp);
    }

    // ---- Block reduction -> one atomic per block ----
#pragma unroll
    for (int o = 16; o > 0; o >>= 1)
        local += __shfl_xor_sync(0xffffffffu, local, o);
    if ((threadIdx.x & 31) == 0) sred[threadIdx.x >> 5] = local;
    __syncthreads();
    if (threadIdx.x < 8) {
        float v = sred[threadIdx.x];
#pragma unroll
        for (int o = 4; o > 0; o >>= 1)
            v += __shfl_xor_sync(0x000000ffu, v, o);
        if (threadIdx.x == 0) {
            const float inv_np = 1.0f / (float)(BB * HH * WW);
            atomicAdd(out, v * inv_np);
        }
    }
}

extern "C" void kernel_launch(void* const* d_in, const int* in_sizes, int n_in,
                              void* d_out, int out_size) {
    const float* logits = (const float*)d_in[0];   // depth_logits (B,C,H,W) f32
    const float* boxes  = (const float*)d_in[1];   // gt_boxes2d (B*N,4) f32
    // d_in[2] = num_gt_per_img (scalar int, constant 16 for this shape)
    const float* depths = (const float*)d_in[3];   // gt_center_depth (B*N,) f32
    float* out = (float*)d_out;

    cudaMemsetAsync(out, 0, sizeof(float), 0);

    const int total_groups = BB * (HH * WW) / 2;   // 122880 threads (2 px each)
    const int threads = 256;
    const int blocks  = total_groups / threads;    // 480
    ddn_loss_kernel<<<blocks, threads>>>(logits, boxes, depths, out);
}